// round 14
// baseline (speedup 1.0000x reference)
#include <cuda_runtime.h>
#include <cuda_fp16.h>
#include <cstdint>

// Problem constants
#define T_STEPS 512
#define BATCH   256
#define DIN     128
#define HID     512
#define KTOT    640          // DIN + HID

// Tiling: 256 CTAs (2 per SM where paired). CTA (gb, jn): 16 batch rows, 32 H cols.
#define P_B 16               // batch groups
#define P_N 16               // n-slices per group
#define B_TILE 16            // batch rows per CTA (M)
#define N_SLICE 32           // H columns per CTA
#define NCHUNK 5             // 640 / 128
#define NKG 8                // kg16 groups per chunk
#define KGG_TOT 40           // 640 / 16
#define NTHREADS 256
#define GRID (P_B * P_N)     // 256

// Shared memory (uint32 units). Weight staging (20480 u32 = 80KB) is ALIASED
// over the runtime layout: it is only used during init, before z/epi exist.
#define OFF_WF  0            // staging: 40*4*32*4 = 20480 u32
#define OFF_Z   0            // 6 slots * 1024 u32 = 6144
#define OFF_EPI 6144         // 4 wk-buffers * 16*66 = 4224
#define OFF_BC  10368        // 32
#define OFF_BT  10400        // 32
#define OFF_WO  10432        // 512
#define SMEM_U32 20480
#define SMEM_BYTES (SMEM_U32 * 4)   // 81920 B -> 2 CTAs/SM

#define ZBUF_BYTES 4096      // 16 rows x 256 B

// Persistent device state.
// g_hz: hidden state fp16, PRE-SWIZZLED smem fragment layout, [buf][group][chunk].
__device__ __align__(16) char g_hz[2][P_B][4][ZBUF_BYTES];
__device__ unsigned g_count[P_B];   // zero-init; returns to 0 each launch
__device__ unsigned g_sense[P_B];   // 512 toggles/launch -> back to 0 (replay-safe)

__device__ __forceinline__ void mma_f16(float* c, unsigned a0, unsigned a1,
                                        unsigned a2, unsigned a3,
                                        unsigned b0, unsigned b1) {
    asm("mma.sync.aligned.m16n8k16.row.col.f32.f16.f16.f32 "
        "{%0,%1,%2,%3},{%4,%5,%6,%7},{%8,%9},{%0,%1,%2,%3};"
        : "+f"(c[0]), "+f"(c[1]), "+f"(c[2]), "+f"(c[3])
        : "r"(a0), "r"(a1), "r"(a2), "r"(a3), "r"(b0), "r"(b1));
}

__device__ __forceinline__ void ldsm_x4(unsigned& a0, unsigned& a1,
                                        unsigned& a2, unsigned& a3, unsigned saddr) {
    asm volatile("ldmatrix.sync.aligned.m8n8.x4.shared.b16 {%0,%1,%2,%3}, [%4];"
                 : "=r"(a0), "=r"(a1), "=r"(a2), "=r"(a3) : "r"(saddr));
}

// Store one fp32 chunk (16 rows x 128 k) into smem as fp16; XOR swizzle on the
// COMPLETE low-12-bit byte offset: (m*256 + k*2) ^ ((m&7)<<4). x chunks only.
__device__ __forceinline__ void st_chunk(const float4* v, char* zbuf, int tid) {
#pragma unroll
    for (int i = 0; i < 2; i++) {
        int f  = i * NTHREADS + tid;       // 0..511 float4s
        int m  = f >> 5;                   // row 0..15
        int k4 = (f & 31) * 4;
        unsigned off = (unsigned)(m * 256 + k4 * 2) ^ (((unsigned)m & 7u) << 4);
        __half2 h01 = __float22half2_rn(make_float2(v[i].x, v[i].y));
        __half2 h23 = __float22half2_rn(make_float2(v[i].z, v[i].w));
        uint2 pk;
        pk.x = *(unsigned*)&h01;
        pk.y = *(unsigned*)&h23;
        *(uint2*)(zbuf + off) = pk;
    }
}

__global__ void __launch_bounds__(NTHREADS, 2)
liquid_kernel(const float* __restrict__ x_seq,
              const float* __restrict__ Wc, const float* __restrict__ bc,
              const float* __restrict__ Wt, const float* __restrict__ bt,
              const float* __restrict__ Wo, const float* __restrict__ bo,
              float* __restrict__ out) {
    extern __shared__ unsigned smem[];
    unsigned* sWf  = smem + OFF_WF;      // init only (aliased)
    char*     sZ   = (char*)(smem + OFF_Z);
    float*    sEpi = (float*)(smem + OFF_EPI);
    float*    sBc  = (float*)(smem + OFF_BC);
    float*    sBt  = (float*)(smem + OFF_BT);
    float*    sWo  = (float*)(smem + OFF_WO);

    const int tid  = threadIdx.x;
    const int gb   = blockIdx.x / P_N;   // batch group 0..15
    const int jn   = blockIdx.x % P_N;   // n-slice 0..15
    const int b0   = gb * B_TILE;
    const int n0   = jn * N_SLICE;
    const int lane = tid & 31;
    const int wid  = tid >> 5;           // 0..7
    const int wn   = wid & 1;            // N half (32 combined cols)
    const int wk   = wid >> 1;           // K quarter (2 kg16 per chunk)

    // ---- init: weights into B-fragment layout (fp16) in staging region ----
    for (int e = tid; e < KGG_TOT * 4 * 32 * 4; e += NTHREADS) {
        int q    = e & 3;
        int l    = (e >> 2) & 31;
        int ntp  = (e >> 7) & 3;
        int kgg  = e >> 9;
        int nt   = 2 * ntp + (q >> 1);
        int k0   = kgg * 16 + (l & 3) * 2 + (q & 1) * 8;
        int cc   = nt * 8 + (l >> 2);
        const float* W = (cc < N_SLICE) ? (Wc + n0 + cc) : (Wt + n0 + cc - N_SLICE);
        float w0 = W[(size_t)k0 * HID];
        float w1 = W[(size_t)(k0 + 1) * HID];
        __half2 h = __float22half2_rn(make_float2(w0, w1));
        sWf[e] = *(unsigned*)&h;
    }
    __syncthreads();

    // ---- this warp's B fragments -> REGISTERS (persistent) ----
    uint4 bf[10][2];
#pragma unroll
    for (int t = 0; t < 10; t++) {
        int kgg = (t >> 1) * NKG + wk * 2 + (t & 1);
#pragma unroll
        for (int tp = 0; tp < 2; tp++) {
            int ntp = wn * 2 + tp;
            bf[t][tp] = *(const uint4*)(sWf + ((kgg * 4 + ntp) * 32 + lane) * 4);
        }
    }
    __syncthreads();   // ALL reads of staging done before aliased writes below

    // ---- runtime smem init (aliased over staging) ----
    if (tid < N_SLICE) { sBc[tid] = bc[n0 + tid]; sBt[tid] = bt[n0 + tid]; }
#pragma unroll
    for (int r = 0; r < 2; r++) sWo[r * NTHREADS + tid] = Wo[r * NTHREADS + tid];
    const float bo_v = bo[0];

    // Per-thread staging coordinates for x chunks (step-invariant)
    const int sm0 = tid >> 5;                 // 0..7
    const int sk0 = (tid & 31) * 4;
    const int sm1 = (NTHREADS + tid) >> 5;    // 8..15

    // ldmatrix base offsets; swizzle on complete low-12-bit offset; slot adds
    // bits 12+ (carry-free).
    const int arow = ((lane >> 3) & 1) * 8 + (lane & 7);   // 0..15
    const int acol = ((lane >> 4) & 1) * 16;
    const unsigned zsh = (unsigned)__cvta_generic_to_shared(sZ);
    unsigned aoff[2];
#pragma unroll
    for (int i = 0; i < 2; i++) {
        int kg = wk * 2 + i;
        aoff[i] = zsh + (((unsigned)(arow * 256 + kg * 32 + acol)) ^
                         (((unsigned)arow & 7u) << 4));
    }

    // Per-warp self-slice cp.async offsets: this warp's ldsm footprint for a
    // chunk is rows 0..15 x kg {wk*2, wk*2+1} x 32B. Lane covers (row, half).
    const int crow  = lane >> 1;
    const int chalf = (lane & 1) * 16;
    unsigned coff[2];
#pragma unroll
    for (int i = 0; i < 2; i++) {
        coff[i] = ((unsigned)(crow * 256 + (wk * 2 + i) * 32 + chalf)) ^
                  (((unsigned)crow & 7u) << 4);
    }

    // Epilogue h-store pointers (2 elements: rows wid and 8+wid, col n0+lane)
    const int hcol = n0 + lane;
    char* const hz_w0 = &g_hz[0][gb][hcol >> 7]
        [((unsigned)((wid) * 256 + (hcol & 127) * 2)) ^ (((unsigned)wid & 7u) << 4)];
    char* const hz_w1 = &g_hz[0][gb][hcol >> 7]
        [((unsigned)((8 + wid) * 256 + (hcol & 127) * 2)) ^ (((unsigned)(8 + wid) & 7u) << 4)];
    const size_t hz_buf_stride = (size_t)P_B * 4 * ZBUF_BYTES;

    // y-dot row offset (warp 0 computes group row jn)
    const unsigned yoff = ((unsigned)(jn * 256 + lane * 8)) ^
                          (((unsigned)jn & 7u) << 4);

    float h_loc[2] = {0.f, 0.f};

    // Prologue: zero h slots (2..5); stage x(0) into slot 0
    {
        uint4 z4 = make_uint4(0u, 0u, 0u, 0u);
#pragma unroll
        for (int c = 0; c < 4; c++)
            *((uint4*)(sZ + (2 + c) * ZBUF_BYTES) + tid) = z4;
        float4 vx0[2];
        const float* src = x_seq + (size_t)b0 * DIN;
        vx0[0] = *(const float4*)(src + (size_t)sm0 * DIN + sk0);
        vx0[1] = *(const float4*)(src + (size_t)sm1 * DIN + sk0);
        st_chunk(vx0, sZ, tid);
    }
    __syncthreads();

    unsigned lsense = 0;

    for (int s = 0; s < T_STEPS; s++) {
        const int p = s & 1;

        // ---- issue next x LDG (entire step to land) ----
        float4 vx[2];
        if (s + 1 < T_STEPS) {
            const float* src = x_seq + ((size_t)(s + 1) * BATCH + b0) * DIN;
            vx[0] = *(const float4*)(src + (size_t)sm0 * DIN + sk0);
            vx[1] = *(const float4*)(src + (size_t)sm1 * DIN + sk0);
        }

        // ---- WAIT for barrier(s-1): h(s) becomes visible (tid0) ----
        if (s > 0 && tid == 0) {
            unsigned v;
            do {
                asm volatile("ld.acquire.gpu.global.u32 %0, [%1];"
                             : "=r"(v) : "l"(&g_sense[gb]) : "memory");
            } while (v != lsense);
        }
        __syncthreads();                      // BAR 1

        // ---- per-warp cp.async of THIS WARP'S h footprint (2 groups) ----
        if (s > 0) {
            const char* hb = &g_hz[p][gb][0][0];
#pragma unroll
            for (int c = 0; c < 2; c++)       // slots 2,3
#pragma unroll
                for (int i = 0; i < 2; i++)
                    asm volatile("cp.async.cg.shared.global [%0], [%1], 16;"
                                 :: "r"(zsh + (unsigned)(2 + c) * ZBUF_BYTES + coff[i]),
                                    "l"(hb + (size_t)c * ZBUF_BYTES + coff[i]) : "memory");
            asm volatile("cp.async.commit_group;" ::: "memory");
#pragma unroll
            for (int c = 2; c < 4; c++)       // slots 4,5
#pragma unroll
                for (int i = 0; i < 2; i++)
                    asm volatile("cp.async.cg.shared.global [%0], [%1], 16;"
                                 :: "r"(zsh + (unsigned)(2 + c) * ZBUF_BYTES + coff[i]),
                                    "l"(hb + (size_t)c * ZBUF_BYTES + coff[i]) : "memory");
            asm volatile("cp.async.commit_group;" ::: "memory");
        }

        // ---- chunk-0 MMA (x slot p, local) fills group-1 latency ----
        float acc[4][4] = {};
        const unsigned x0off = (unsigned)(p * ZBUF_BYTES);
#pragma unroll
        for (int t = 0; t < 2; t++) {
            unsigned a0, a1, a2, a3;
            ldsm_x4(a0, a1, a2, a3, aoff[t] + x0off);
#pragma unroll
            for (int tp = 0; tp < 2; tp++) {
                mma_f16(acc[tp * 2 + 0], a0, a1, a2, a3, bf[t][tp].x, bf[t][tp].y);
                mma_f16(acc[tp * 2 + 1], a0, a1, a2, a3, bf[t][tp].z, bf[t][tp].w);
            }
        }

        // ---- warp-local wait: this warp's slots 2,3 slice staged ----
        if (s > 0) {
            asm volatile("cp.async.wait_group 1;" ::: "memory");
            __syncwarp();
        }

        // ---- chunks 1..2 MMA (slots 2,3) fill group-2 latency ----
#pragma unroll
        for (int t = 2; t < 6; t++) {
            unsigned c = (unsigned)(t >> 1);  // 1..2
            unsigned a0, a1, a2, a3;
            ldsm_x4(a0, a1, a2, a3, aoff[t & 1] + (c + 1) * ZBUF_BYTES);
#pragma unroll
            for (int tp = 0; tp < 2; tp++) {
                mma_f16(acc[tp * 2 + 0], a0, a1, a2, a3, bf[t][tp].x, bf[t][tp].y);
                mma_f16(acc[tp * 2 + 1], a0, a1, a2, a3, bf[t][tp].z, bf[t][tp].w);
            }
        }

        if (s > 0) {
            asm volatile("cp.async.wait_group 0;" ::: "memory");
            __syncwarp();
        }

        // ---- chunks 3..4 MMA (slots 4,5) ----
#pragma unroll
        for (int t = 6; t < 10; t++) {
            unsigned c = (unsigned)(t >> 1);  // 3..4
            unsigned a0, a1, a2, a3;
            ldsm_x4(a0, a1, a2, a3, aoff[t & 1] + (c + 1) * ZBUF_BYTES);
#pragma unroll
            for (int tp = 0; tp < 2; tp++) {
                mma_f16(acc[tp * 2 + 0], a0, a1, a2, a3, bf[t][tp].x, bf[t][tp].y);
                mma_f16(acc[tp * 2 + 1], a0, a1, a2, a3, bf[t][tp].z, bf[t][tp].w);
            }
        }

        // ---- scatter partial accumulators to per-wk epilogue buffers ----
        {
            float* eb = sEpi + wk * 1056;
            int row = lane >> 2;              // 0..7
#pragma unroll
            for (int t = 0; t < 4; t++) {
                int col = wn * 32 + t * 8 + (lane & 3) * 2;
                *(float2*)&eb[row * 66 + col]       = make_float2(acc[t][0], acc[t][1]);
                *(float2*)&eb[(row + 8) * 66 + col] = make_float2(acc[t][2], acc[t][3]);
            }
        }
        __syncthreads();                      // BAR 2: sEpi complete

        // ---- epilogue: reduce wk partials, activations, h update ----
        float tau_sv[2];
        char* hz_base0 = hz_w0 + (size_t)(p ^ 1) * hz_buf_stride;
        char* hz_base1 = hz_w1 + (size_t)(p ^ 1) * hz_buf_stride;
#pragma unroll
        for (int i = 0; i < 2; i++) {
            int b  = i * 8 + wid;             // local batch row 0..15
            int nl = lane;
            float uc = sBc[nl], ut = sBt[nl];
#pragma unroll
            for (int q = 0; q < 4; q++) {
                uc += sEpi[q * 1056 + b * 66 + nl];
                ut += sEpi[q * 1056 + b * 66 + nl + 32];
            }
            float ea   = __expf(-2.f * fabsf(uc));
            float cand = copysignf(__fdividef(1.f - ea, 1.f + ea), uc);
            float sg   = __fdividef(1.f, 1.f + __expf(-ut));
            float tau  = 0.2f + 1.8f * sg;
            tau_sv[i]  = tau;
            float h    = h_loc[i];
            float hn   = h + 0.1f * __fdividef(cand - h, tau);
            h_loc[i]   = hn;
            *(__half*)(i == 0 ? hz_base0 : hz_base1) = __float2half_rn(hn);
        }

        // ---- BAR then ARRIVE IMMEDIATELY (critical path to peers) ----
        __syncthreads();                      // BAR 3: all h stores issued+ordered
        lsense ^= 1u;
        if (tid == 0) {
            unsigned old;
            asm volatile("atom.add.release.gpu.global.u32 %0, [%1], %2;"
                         : "=r"(old) : "l"(&g_count[gb]), "r"(1u) : "memory");
            if (old == P_N - 1u) {
                g_count[gb] = 0u;
                asm volatile("st.release.gpu.global.u32 [%0], %1;"
                             :: "l"(&g_sense[gb]), "r"(lsense) : "memory");
            }
        }

        // ---- post-arrive tail (not on peers' critical path) ----
        // y(s-1): warp 0 dots staged h(s) row jn with Wo (slots 2..5 still valid)
        if (s > 0 && wid == 0) {
            float y = 0.f;
#pragma unroll
            for (int c = 0; c < 4; c++) {
                uint2 hh = *(const uint2*)(sZ + (2 + c) * ZBUF_BYTES + yoff);
                float4 w4 = *(const float4*)&sWo[c * 128 + lane * 4];
                float2 f0 = __half22float2(*(__half2*)&hh.x);
                float2 f1 = __half22float2(*(__half2*)&hh.y);
                y += f0.x * w4.x + f0.y * w4.y + f1.x * w4.z + f1.y * w4.w;
            }
#pragma unroll
            for (int o = 16; o; o >>= 1) y += __shfl_xor_sync(0xffffffffu, y, o);
            if (lane == 0) out[(size_t)(s - 1) * BATCH + b0 + jn] = y + bo_v;
        }
        // stage next x into slot p^1 (read next step only after BAR 1)
        if (s + 1 < T_STEPS) st_chunk(vx, sZ + (p ^ 1) * ZBUF_BYTES, tid);
        // tau stores (never read cross-CTA)
#pragma unroll
        for (int i = 0; i < 2; i++) {
            int b = i * 8 + wid;
            __stcs(&out[(size_t)T_STEPS * BATCH +
                        ((size_t)s * BATCH + b0 + b) * HID + n0 + lane], tau_sv[i]);
        }
    }

    // ---- final: wait barrier(511), then y(511) from g_hz[0] ----
    if (tid == 0) {
        unsigned v;
        do {
            asm volatile("ld.acquire.gpu.global.u32 %0, [%1];"
                         : "=r"(v) : "l"(&g_sense[gb]) : "memory");
        } while (v != lsense);
    }
    __syncthreads();
    if (wid == 0) {
        const char* hb = (const char*)&g_hz[0][gb][0][0];
        float y = 0.f;
#pragma unroll
        for (int c = 0; c < 4; c++) {
            uint2 hh = __ldcg((const uint2*)(hb + c * ZBUF_BYTES + yoff));
            float4 w4 = *(const float4*)&sWo[c * 128 + lane * 4];
            float2 f0 = __half22float2(*(__half2*)&hh.x);
            float2 f1 = __half22float2(*(__half2*)&hh.y);
            y += f0.x * w4.x + f0.y * w4.y + f1.x * w4.z + f1.y * w4.w;
        }
#pragma unroll
        for (int o = 16; o; o >>= 1) y += __shfl_xor_sync(0xffffffffu, y, o);
        if (lane == 0) out[(size_t)(T_STEPS - 1) * BATCH + b0 + jn] = y + bo_v;
    }
}

extern "C" void kernel_launch(void* const* d_in, const int* in_sizes, int n_in,
                              void* d_out, int out_size) {
    (void)in_sizes; (void)n_in; (void)out_size;
    const float* x_seq = (const float*)d_in[0];
    const float* Wc    = (const float*)d_in[1];
    const float* bc    = (const float*)d_in[2];
    const float* Wt    = (const float*)d_in[3];
    const float* bt    = (const float*)d_in[4];
    const float* Wo    = (const float*)d_in[5];
    const float* bo    = (const float*)d_in[6];
    float* out = (float*)d_out;

    cudaFuncSetAttribute(liquid_kernel, cudaFuncAttributeMaxDynamicSharedMemorySize, SMEM_BYTES);
    liquid_kernel<<<GRID, NTHREADS, SMEM_BYTES>>>(x_seq, Wc, bc, Wt, bt, Wo, bo, out);
}

// round 15
// speedup vs baseline: 1.0724x; 1.0724x over previous
#include <cuda_runtime.h>
#include <cuda_fp16.h>
#include <cstdint>

// Problem constants
#define T_STEPS 512
#define BATCH   256
#define DIN     128
#define HID     512
#define KTOT    640          // DIN + HID

// Tiling: 256 CTAs (2 per SM where paired). CTA (gb, jn): 16 batch rows, 32 H cols.
#define P_B 16               // batch groups
#define P_N 16               // n-slices per group
#define B_TILE 16            // batch rows per CTA (M)
#define N_SLICE 32           // H columns per CTA
#define NCHUNK 5             // 640 / 128
#define NKG 8                // kg16 groups per chunk
#define KGG_TOT 40           // 640 / 16
#define NTHREADS 256
#define GRID (P_B * P_N)     // 256

// Shared memory (uint32 units). Weight staging (20480 u32 = 80KB) is ALIASED
// over the runtime layout: it is only used during init, before z/epi exist.
#define OFF_WF  0            // staging: 40*4*32*4 = 20480 u32
#define OFF_Z   0            // 6 slots * 1024 u32 = 6144
#define OFF_EPI 6144         // 4 wk-buffers * 16*66 = 4224
#define OFF_BC  10368        // 32
#define OFF_BT  10400        // 32
#define OFF_WO  10432        // 512
#define SMEM_U32 20480
#define SMEM_BYTES (SMEM_U32 * 4)   // 81920 B -> 2 CTAs/SM

#define ZBUF_BYTES 4096      // 16 rows x 256 B

// Persistent device state.
// g_hz: hidden state fp16, PRE-SWIZZLED smem fragment layout, [buf][group][chunk].
__device__ __align__(16) char g_hz[2][P_B][4][ZBUF_BYTES];
__device__ unsigned g_count[P_B];   // zero-init; returns to 0 each launch
__device__ unsigned g_sense[P_B];   // 512 toggles/launch -> back to 0 (replay-safe)

__device__ __forceinline__ void mma_f16(float* c, unsigned a0, unsigned a1,
                                        unsigned a2, unsigned a3,
                                        unsigned b0, unsigned b1) {
    asm("mma.sync.aligned.m16n8k16.row.col.f32.f16.f16.f32 "
        "{%0,%1,%2,%3},{%4,%5,%6,%7},{%8,%9},{%0,%1,%2,%3};"
        : "+f"(c[0]), "+f"(c[1]), "+f"(c[2]), "+f"(c[3])
        : "r"(a0), "r"(a1), "r"(a2), "r"(a3), "r"(b0), "r"(b1));
}

__device__ __forceinline__ void ldsm_x4(unsigned& a0, unsigned& a1,
                                        unsigned& a2, unsigned& a3, unsigned saddr) {
    asm volatile("ldmatrix.sync.aligned.m8n8.x4.shared.b16 {%0,%1,%2,%3}, [%4];"
                 : "=r"(a0), "=r"(a1), "=r"(a2), "=r"(a3) : "r"(saddr));
}

// Store one fp32 chunk (16 rows x 128 k) into smem as fp16; XOR swizzle on the
// COMPLETE low-12-bit byte offset: (m*256 + k*2) ^ ((m&7)<<4). x chunks only.
__device__ __forceinline__ void st_chunk(const float4* v, char* zbuf, int tid) {
#pragma unroll
    for (int i = 0; i < 2; i++) {
        int f  = i * NTHREADS + tid;       // 0..511 float4s
        int m  = f >> 5;                   // row 0..15
        int k4 = (f & 31) * 4;
        unsigned off = (unsigned)(m * 256 + k4 * 2) ^ (((unsigned)m & 7u) << 4);
        __half2 h01 = __float22half2_rn(make_float2(v[i].x, v[i].y));
        __half2 h23 = __float22half2_rn(make_float2(v[i].z, v[i].w));
        uint2 pk;
        pk.x = *(unsigned*)&h01;
        pk.y = *(unsigned*)&h23;
        *(uint2*)(zbuf + off) = pk;
    }
}

__global__ void __launch_bounds__(NTHREADS, 2)
liquid_kernel(const float* __restrict__ x_seq,
              const float* __restrict__ Wc, const float* __restrict__ bc,
              const float* __restrict__ Wt, const float* __restrict__ bt,
              const float* __restrict__ Wo, const float* __restrict__ bo,
              float* __restrict__ out) {
    extern __shared__ unsigned smem[];
    unsigned* sWf  = smem + OFF_WF;      // init only (aliased)
    char*     sZ   = (char*)(smem + OFF_Z);
    float*    sEpi = (float*)(smem + OFF_EPI);
    float*    sBc  = (float*)(smem + OFF_BC);
    float*    sBt  = (float*)(smem + OFF_BT);
    float*    sWo  = (float*)(smem + OFF_WO);

    const int tid  = threadIdx.x;
    const int gb   = blockIdx.x / P_N;   // batch group 0..15
    const int jn   = blockIdx.x % P_N;   // n-slice 0..15
    const int b0   = gb * B_TILE;
    const int n0   = jn * N_SLICE;
    const int lane = tid & 31;
    const int wid  = tid >> 5;           // 0..7
    const int wn   = wid & 1;            // N half (32 combined cols)
    const int wk   = wid >> 1;           // K quarter (2 kg16 per chunk)

    // ---- init: weights into B-fragment layout (fp16) in staging region ----
    for (int e = tid; e < KGG_TOT * 4 * 32 * 4; e += NTHREADS) {
        int q    = e & 3;
        int l    = (e >> 2) & 31;
        int ntp  = (e >> 7) & 3;
        int kgg  = e >> 9;
        int nt   = 2 * ntp + (q >> 1);
        int k0   = kgg * 16 + (l & 3) * 2 + (q & 1) * 8;
        int cc   = nt * 8 + (l >> 2);
        const float* W = (cc < N_SLICE) ? (Wc + n0 + cc) : (Wt + n0 + cc - N_SLICE);
        float w0 = W[(size_t)k0 * HID];
        float w1 = W[(size_t)(k0 + 1) * HID];
        __half2 h = __float22half2_rn(make_float2(w0, w1));
        sWf[e] = *(unsigned*)&h;
    }
    __syncthreads();

    // ---- this warp's B fragments -> REGISTERS (persistent) ----
    uint4 bf[10][2];
#pragma unroll
    for (int t = 0; t < 10; t++) {
        int kgg = (t >> 1) * NKG + wk * 2 + (t & 1);
#pragma unroll
        for (int tp = 0; tp < 2; tp++) {
            int ntp = wn * 2 + tp;
            bf[t][tp] = *(const uint4*)(sWf + ((kgg * 4 + ntp) * 32 + lane) * 4);
        }
    }
    __syncthreads();   // ALL reads of staging done before aliased writes below

    // ---- runtime smem init (aliased over staging) ----
    if (tid < N_SLICE) { sBc[tid] = bc[n0 + tid]; sBt[tid] = bt[n0 + tid]; }
#pragma unroll
    for (int r = 0; r < 2; r++) sWo[r * NTHREADS + tid] = Wo[r * NTHREADS + tid];
    const float bo_v = bo[0];

    // Per-thread staging coordinates for x chunks (step-invariant)
    const int sm0 = tid >> 5;                 // 0..7
    const int sk0 = (tid & 31) * 4;
    const int sm1 = (NTHREADS + tid) >> 5;    // 8..15

    // ldmatrix base offsets; swizzle on complete low-12-bit offset; slot adds
    // bits 12+ (carry-free).
    const int arow = ((lane >> 3) & 1) * 8 + (lane & 7);   // 0..15
    const int acol = ((lane >> 4) & 1) * 16;
    const unsigned zsh = (unsigned)__cvta_generic_to_shared(sZ);
    unsigned aoff[2];
#pragma unroll
    for (int i = 0; i < 2; i++) {
        int kg = wk * 2 + i;
        aoff[i] = zsh + (((unsigned)(arow * 256 + kg * 32 + acol)) ^
                         (((unsigned)arow & 7u) << 4));
    }

    // Epilogue h-store pointers (2 elements: rows wid and 8+wid, col n0+lane)
    const int hcol = n0 + lane;
    char* const hz_w0 = &g_hz[0][gb][hcol >> 7]
        [((unsigned)((wid) * 256 + (hcol & 127) * 2)) ^ (((unsigned)wid & 7u) << 4)];
    char* const hz_w1 = &g_hz[0][gb][hcol >> 7]
        [((unsigned)((8 + wid) * 256 + (hcol & 127) * 2)) ^ (((unsigned)(8 + wid) & 7u) << 4)];
    const size_t hz_buf_stride = (size_t)P_B * 4 * ZBUF_BYTES;

    // y-dot row offset (warp 0 computes group row jn)
    const unsigned yoff = ((unsigned)(jn * 256 + lane * 8)) ^
                          (((unsigned)jn & 7u) << 4);

    float h_loc[2] = {0.f, 0.f};

    // Prologue: zero h slots (2..5); stage x(0) into slot 0
    {
        uint4 z4 = make_uint4(0u, 0u, 0u, 0u);
#pragma unroll
        for (int c = 0; c < 4; c++)
            *((uint4*)(sZ + (2 + c) * ZBUF_BYTES) + tid) = z4;
        float4 vx0[2];
        const float* src = x_seq + (size_t)b0 * DIN;
        vx0[0] = *(const float4*)(src + (size_t)sm0 * DIN + sk0);
        vx0[1] = *(const float4*)(src + (size_t)sm1 * DIN + sk0);
        st_chunk(vx0, sZ, tid);
    }
    __syncthreads();

    unsigned lsense = 0;

    for (int s = 0; s < T_STEPS; s++) {
        const int p = s & 1;

        // ---- issue next x LDG (entire step to land) ----
        float4 vx[2];
        if (s + 1 < T_STEPS) {
            const float* src = x_seq + ((size_t)(s + 1) * BATCH + b0) * DIN;
            vx[0] = *(const float4*)(src + (size_t)sm0 * DIN + sk0);
            vx[1] = *(const float4*)(src + (size_t)sm1 * DIN + sk0);
        }

        // ---- WAIT for barrier(s-1): h(s) becomes visible (tid0) ----
        if (s > 0 && tid == 0) {
            unsigned v;
            do {
                asm volatile("ld.acquire.gpu.global.u32 %0, [%1];"
                             : "=r"(v) : "l"(&g_sense[gb]) : "memory");
            } while (v != lsense);
        }
        __syncthreads();                      // BAR 1

        // ---- block-wide coalesced cp.async of h slots 2..5 (2 groups) ----
        if (s > 0) {
            const char* hb = &g_hz[p][gb][0][0] + (size_t)tid * 16;
            unsigned dst = zsh + 2u * ZBUF_BYTES + (unsigned)tid * 16u;
#pragma unroll
            for (int c = 0; c < 2; c++)       // slots 2,3
                asm volatile("cp.async.cg.shared.global [%0], [%1], 16;"
                             :: "r"(dst + (unsigned)c * ZBUF_BYTES),
                                "l"(hb + (size_t)c * ZBUF_BYTES) : "memory");
            asm volatile("cp.async.commit_group;" ::: "memory");
#pragma unroll
            for (int c = 2; c < 4; c++)       // slots 4,5
                asm volatile("cp.async.cg.shared.global [%0], [%1], 16;"
                             :: "r"(dst + (unsigned)c * ZBUF_BYTES),
                                "l"(hb + (size_t)c * ZBUF_BYTES) : "memory");
            asm volatile("cp.async.commit_group;" ::: "memory");
        }

        // ---- chunk-0 MMA (x slot p, local) fills group-1 latency ----
        float acc[4][4] = {};
        const unsigned x0off = (unsigned)(p * ZBUF_BYTES);
#pragma unroll
        for (int t = 0; t < 2; t++) {
            unsigned a0, a1, a2, a3;
            ldsm_x4(a0, a1, a2, a3, aoff[t] + x0off);
#pragma unroll
            for (int tp = 0; tp < 2; tp++) {
                mma_f16(acc[tp * 2 + 0], a0, a1, a2, a3, bf[t][tp].x, bf[t][tp].y);
                mma_f16(acc[tp * 2 + 1], a0, a1, a2, a3, bf[t][tp].z, bf[t][tp].w);
            }
        }

        if (s > 0) asm volatile("cp.async.wait_group 1;" ::: "memory");
        __syncthreads();                      // BAR 2: slots 2,3 staged

        // ---- chunks 1..2 MMA (slots 2,3) fill group-2 latency ----
#pragma unroll
        for (int t = 2; t < 6; t++) {
            unsigned c = (unsigned)(t >> 1);  // 1..2
            unsigned a0, a1, a2, a3;
            ldsm_x4(a0, a1, a2, a3, aoff[t & 1] + (c + 1) * ZBUF_BYTES);
#pragma unroll
            for (int tp = 0; tp < 2; tp++) {
                mma_f16(acc[tp * 2 + 0], a0, a1, a2, a3, bf[t][tp].x, bf[t][tp].y);
                mma_f16(acc[tp * 2 + 1], a0, a1, a2, a3, bf[t][tp].z, bf[t][tp].w);
            }
        }

        if (s > 0) asm volatile("cp.async.wait_group 0;" ::: "memory");
        __syncthreads();                      // BAR 3: slots 4,5 staged

        // ---- chunks 3..4 MMA (slots 4,5) ----
#pragma unroll
        for (int t = 6; t < 10; t++) {
            unsigned c = (unsigned)(t >> 1);  // 3..4
            unsigned a0, a1, a2, a3;
            ldsm_x4(a0, a1, a2, a3, aoff[t & 1] + (c + 1) * ZBUF_BYTES);
#pragma unroll
            for (int tp = 0; tp < 2; tp++) {
                mma_f16(acc[tp * 2 + 0], a0, a1, a2, a3, bf[t][tp].x, bf[t][tp].y);
                mma_f16(acc[tp * 2 + 1], a0, a1, a2, a3, bf[t][tp].z, bf[t][tp].w);
            }
        }

        // ---- scatter partial accumulators to per-wk epilogue buffers ----
        {
            float* eb = sEpi + wk * 1056;
            int row = lane >> 2;              // 0..7
#pragma unroll
            for (int t = 0; t < 4; t++) {
                int col = wn * 32 + t * 8 + (lane & 3) * 2;
                *(float2*)&eb[row * 66 + col]       = make_float2(acc[t][0], acc[t][1]);
                *(float2*)&eb[(row + 8) * 66 + col] = make_float2(acc[t][2], acc[t][3]);
            }
        }
        __syncthreads();                      // BAR 4: sEpi complete

        // ---- epilogue: reduce wk partials, activations, h update ----
        float tau_sv[2];
        char* hz_base0 = hz_w0 + (size_t)(p ^ 1) * hz_buf_stride;
        char* hz_base1 = hz_w1 + (size_t)(p ^ 1) * hz_buf_stride;
#pragma unroll
        for (int i = 0; i < 2; i++) {
            int b  = i * 8 + wid;             // local batch row 0..15
            int nl = lane;
            float uc = sBc[nl], ut = sBt[nl];
#pragma unroll
            for (int q = 0; q < 4; q++) {
                uc += sEpi[q * 1056 + b * 66 + nl];
                ut += sEpi[q * 1056 + b * 66 + nl + 32];
            }
            float ea   = __expf(-2.f * fabsf(uc));
            float cand = copysignf(__fdividef(1.f - ea, 1.f + ea), uc);
            float sg   = __fdividef(1.f, 1.f + __expf(-ut));
            float tau  = 0.2f + 1.8f * sg;
            tau_sv[i]  = tau;
            float h    = h_loc[i];
            float hn   = h + 0.1f * __fdividef(cand - h, tau);
            h_loc[i]   = hn;
            *(__half*)(i == 0 ? hz_base0 : hz_base1) = __float2half_rn(hn);
        }

        // ---- BAR then ARRIVE IMMEDIATELY (peers' critical path) ----
        __syncthreads();                      // BAR 5: all h stores issued+ordered
        lsense ^= 1u;
        if (tid == 0) {
            unsigned old;
            asm volatile("atom.add.release.gpu.global.u32 %0, [%1], %2;"
                         : "=r"(old) : "l"(&g_count[gb]), "r"(1u) : "memory");
            if (old == P_N - 1u) {
                g_count[gb] = 0u;
                asm volatile("st.release.gpu.global.u32 [%0], %1;"
                             :: "l"(&g_sense[gb]), "r"(lsense) : "memory");
            }
        }

        // ---- post-arrive tail (not on peers' critical path) ----
        // y(s-1): warp 0 dots staged h(s) row jn with Wo (slots 2..5 valid
        // until next step's cp.async, which is after next BAR 1)
        if (s > 0 && wid == 0) {
            float y = 0.f;
#pragma unroll
            for (int c = 0; c < 4; c++) {
                uint2 hh = *(const uint2*)(sZ + (2 + c) * ZBUF_BYTES + yoff);
                float4 w4 = *(const float4*)&sWo[c * 128 + lane * 4];
                float2 f0 = __half22float2(*(__half2*)&hh.x);
                float2 f1 = __half22float2(*(__half2*)&hh.y);
                y += f0.x * w4.x + f0.y * w4.y + f1.x * w4.z + f1.y * w4.w;
            }
#pragma unroll
            for (int o = 16; o; o >>= 1) y += __shfl_xor_sync(0xffffffffu, y, o);
            if (lane == 0) out[(size_t)(s - 1) * BATCH + b0 + jn] = y + bo_v;
        }
        // stage next x into slot p^1 (reads happen only after next BAR 1)
        if (s + 1 < T_STEPS) st_chunk(vx, sZ + (p ^ 1) * ZBUF_BYTES, tid);
        // tau stores (never read cross-CTA)
#pragma unroll
        for (int i = 0; i < 2; i++) {
            int b = i * 8 + wid;
            __stcs(&out[(size_t)T_STEPS * BATCH +
                        ((size_t)s * BATCH + b0 + b) * HID + n0 + lane], tau_sv[i]);
        }
    }

    // ---- final: wait barrier(511), then y(511) from g_hz[0] ----
    if (tid == 0) {
        unsigned v;
        do {
            asm volatile("ld.acquire.gpu.global.u32 %0, [%1];"
                         : "=r"(v) : "l"(&g_sense[gb]) : "memory");
        } while (v != lsense);
    }
    __syncthreads();
    if (wid == 0) {
        const char* hb = (const char*)&g_hz[0][gb][0][0];
        float y = 0.f;
#pragma unroll
        for (int c = 0; c < 4; c++) {
            uint2 hh = __ldcg((const uint2*)(hb + c * ZBUF_BYTES + yoff));
            float4 w4 = *(const float4*)&sWo[c * 128 + lane * 4];
            float2 f0 = __half22float2(*(__half2*)&hh.x);
            float2 f1 = __half22float2(*(__half2*)&hh.y);
            y += f0.x * w4.x + f0.y * w4.y + f1.x * w4.z + f1.y * w4.w;
        }
#pragma unroll
        for (int o = 16; o; o >>= 1) y += __shfl_xor_sync(0xffffffffu, y, o);
        if (lane == 0) out[(size_t)(T_STEPS - 1) * BATCH + b0 + jn] = y + bo_v;
    }
}

extern "C" void kernel_launch(void* const* d_in, const int* in_sizes, int n_in,
                              void* d_out, int out_size) {
    (void)in_sizes; (void)n_in; (void)out_size;
    const float* x_seq = (const float*)d_in[0];
    const float* Wc    = (const float*)d_in[1];
    const float* bc    = (const float*)d_in[2];
    const float* Wt    = (const float*)d_in[3];
    const float* bt    = (const float*)d_in[4];
    const float* Wo    = (const float*)d_in[5];
    const float* bo    = (const float*)d_in[6];
    float* out = (float*)d_out;

    cudaFuncSetAttribute(liquid_kernel, cudaFuncAttributeMaxDynamicSharedMemorySize, SMEM_BYTES);
    liquid_kernel<<<GRID, NTHREADS, SMEM_BYTES>>>(x_seq, Wc, bc, Wt, bt, Wo, bo, out);
}

// round 16
// speedup vs baseline: 1.3660x; 1.2738x over previous
#include <cuda_runtime.h>
#include <cuda_fp16.h>
#include <cstdint>

// Problem constants
#define T_STEPS 512
#define BATCH   256
#define DIN     128
#define HID     512
#define KTOT    640          // DIN + HID

// Tiling: 256 CTAs (2 per SM where paired). CTA (gb, jn): 16 batch rows, 32 H cols.
#define P_B 16               // batch groups
#define P_N 16               // n-slices per group
#define B_TILE 16            // batch rows per CTA (M)
#define N_SLICE 32           // H columns per CTA
#define NCHUNK 5             // 640 / 128
#define NKG 8                // kg16 groups per chunk
#define KGG_TOT 40           // 640 / 16
#define NTHREADS 256
#define GRID (P_B * P_N)     // 256

// Shared memory (uint32 units). Weight staging (20480 u32 = 80KB) is ALIASED
// over the runtime layout: it is only used during init, before z/epi exist.
#define OFF_WF  0            // staging: 40*4*32*4 = 20480 u32
#define OFF_Z   0            // 6 slots * 1024 u32 = 6144
#define OFF_EPI 6144         // 4 wk-buffers * 16*66 = 4224
#define OFF_BC  10368        // 32
#define OFF_BT  10400        // 32
#define OFF_WO  10432        // 512
#define SMEM_U32 20480
#define SMEM_BYTES (SMEM_U32 * 4)   // 81920 B -> 2 CTAs/SM

#define ZBUF_BYTES 4096      // 16 rows x 256 B

// Persistent device state.
// g_hz: hidden state fp16, PRE-SWIZZLED smem fragment layout, [buf][group][chunk].
__device__ __align__(16) char g_hz[2][P_B][4][ZBUF_BYTES];
__device__ unsigned g_count[P_B];   // MONOTONIC arrival count; reset at kernel end
__device__ unsigned g_exit[P_B];    // exit barrier for the reset

__device__ __forceinline__ void mma_f16(float* c, unsigned a0, unsigned a1,
                                        unsigned a2, unsigned a3,
                                        unsigned b0, unsigned b1) {
    asm("mma.sync.aligned.m16n8k16.row.col.f32.f16.f16.f32 "
        "{%0,%1,%2,%3},{%4,%5,%6,%7},{%8,%9},{%0,%1,%2,%3};"
        : "+f"(c[0]), "+f"(c[1]), "+f"(c[2]), "+f"(c[3])
        : "r"(a0), "r"(a1), "r"(a2), "r"(a3), "r"(b0), "r"(b1));
}

__device__ __forceinline__ void ldsm_x4(unsigned& a0, unsigned& a1,
                                        unsigned& a2, unsigned& a3, unsigned saddr) {
    asm volatile("ldmatrix.sync.aligned.m8n8.x4.shared.b16 {%0,%1,%2,%3}, [%4];"
                 : "=r"(a0), "=r"(a1), "=r"(a2), "=r"(a3) : "r"(saddr));
}

// Store one fp32 chunk (16 rows x 128 k) into smem as fp16; XOR swizzle on the
// COMPLETE low-12-bit byte offset: (m*256 + k*2) ^ ((m&7)<<4). x chunks only.
__device__ __forceinline__ void st_chunk(const float4* v, char* zbuf, int tid) {
#pragma unroll
    for (int i = 0; i < 2; i++) {
        int f  = i * NTHREADS + tid;       // 0..511 float4s
        int m  = f >> 5;                   // row 0..15
        int k4 = (f & 31) * 4;
        unsigned off = (unsigned)(m * 256 + k4 * 2) ^ (((unsigned)m & 7u) << 4);
        __half2 h01 = __float22half2_rn(make_float2(v[i].x, v[i].y));
        __half2 h23 = __float22half2_rn(make_float2(v[i].z, v[i].w));
        uint2 pk;
        pk.x = *(unsigned*)&h01;
        pk.y = *(unsigned*)&h23;
        *(uint2*)(zbuf + off) = pk;
    }
}

__global__ void __launch_bounds__(NTHREADS, 2)
liquid_kernel(const float* __restrict__ x_seq,
              const float* __restrict__ Wc, const float* __restrict__ bc,
              const float* __restrict__ Wt, const float* __restrict__ bt,
              const float* __restrict__ Wo, const float* __restrict__ bo,
              float* __restrict__ out) {
    extern __shared__ unsigned smem[];
    unsigned* sWf  = smem + OFF_WF;      // init only (aliased)
    char*     sZ   = (char*)(smem + OFF_Z);
    float*    sEpi = (float*)(smem + OFF_EPI);
    float*    sBc  = (float*)(smem + OFF_BC);
    float*    sBt  = (float*)(smem + OFF_BT);
    float*    sWo  = (float*)(smem + OFF_WO);

    const int tid  = threadIdx.x;
    const int gb   = blockIdx.x / P_N;   // batch group 0..15
    const int jn   = blockIdx.x % P_N;   // n-slice 0..15
    const int b0   = gb * B_TILE;
    const int n0   = jn * N_SLICE;
    const int lane = tid & 31;
    const int wid  = tid >> 5;           // 0..7
    const int wn   = wid & 1;            // N half (32 combined cols)
    const int wk   = wid >> 1;           // K quarter (2 kg16 per chunk)

    // ---- init: weights into B-fragment layout (fp16) in staging region ----
    for (int e = tid; e < KGG_TOT * 4 * 32 * 4; e += NTHREADS) {
        int q    = e & 3;
        int l    = (e >> 2) & 31;
        int ntp  = (e >> 7) & 3;
        int kgg  = e >> 9;
        int nt   = 2 * ntp + (q >> 1);
        int k0   = kgg * 16 + (l & 3) * 2 + (q & 1) * 8;
        int cc   = nt * 8 + (l >> 2);
        const float* W = (cc < N_SLICE) ? (Wc + n0 + cc) : (Wt + n0 + cc - N_SLICE);
        float w0 = W[(size_t)k0 * HID];
        float w1 = W[(size_t)(k0 + 1) * HID];
        __half2 h = __float22half2_rn(make_float2(w0, w1));
        sWf[e] = *(unsigned*)&h;
    }
    __syncthreads();

    // ---- this warp's B fragments -> REGISTERS (persistent) ----
    uint4 bf[10][2];
#pragma unroll
    for (int t = 0; t < 10; t++) {
        int kgg = (t >> 1) * NKG + wk * 2 + (t & 1);
#pragma unroll
        for (int tp = 0; tp < 2; tp++) {
            int ntp = wn * 2 + tp;
            bf[t][tp] = *(const uint4*)(sWf + ((kgg * 4 + ntp) * 32 + lane) * 4);
        }
    }
    __syncthreads();   // ALL reads of staging done before aliased writes below

    // ---- runtime smem init (aliased over staging) ----
    if (tid < N_SLICE) { sBc[tid] = bc[n0 + tid]; sBt[tid] = bt[n0 + tid]; }
#pragma unroll
    for (int r = 0; r < 2; r++) sWo[r * NTHREADS + tid] = Wo[r * NTHREADS + tid];
    const float bo_v = bo[0];

    // Per-thread staging coordinates for x chunks (step-invariant)
    const int sm0 = tid >> 5;                 // 0..7
    const int sk0 = (tid & 31) * 4;
    const int sm1 = (NTHREADS + tid) >> 5;    // 8..15

    // ldmatrix base offsets; swizzle on complete low-12-bit offset; slot adds
    // bits 12+ (carry-free).
    const int arow = ((lane >> 3) & 1) * 8 + (lane & 7);   // 0..15
    const int acol = ((lane >> 4) & 1) * 16;
    const unsigned zsh = (unsigned)__cvta_generic_to_shared(sZ);
    unsigned aoff[2];
#pragma unroll
    for (int i = 0; i < 2; i++) {
        int kg = wk * 2 + i;
        aoff[i] = zsh + (((unsigned)(arow * 256 + kg * 32 + acol)) ^
                         (((unsigned)arow & 7u) << 4));
    }

    // Pair-slice cp.async offset: pair wk (64 lanes = warps wk*2, wk*2+1)
    // copies rows 0..15 x kg {wk*2, wk*2+1} (64B/row) per slot, split by
    // lane-in-pair lg = wn*32+lane: row = lg>>2, 16B quarter q = lg&3.
    const int lg   = wn * 32 + lane;
    const int crow = lg >> 2;
    const unsigned csoff = ((unsigned)(crow * 256 + wk * 64 + (lg & 3) * 16)) ^
                           (((unsigned)crow & 7u) << 4);

    // Epilogue h-store pointers (2 elements: rows wid and 8+wid, col n0+lane)
    const int hcol = n0 + lane;
    char* const hz_w0 = &g_hz[0][gb][hcol >> 7]
        [((unsigned)((wid) * 256 + (hcol & 127) * 2)) ^ (((unsigned)wid & 7u) << 4)];
    char* const hz_w1 = &g_hz[0][gb][hcol >> 7]
        [((unsigned)((8 + wid) * 256 + (hcol & 127) * 2)) ^ (((unsigned)(8 + wid) & 7u) << 4)];
    const size_t hz_buf_stride = (size_t)P_B * 4 * ZBUF_BYTES;

    // y-dot row offset (warp 0 computes group row jn)
    const unsigned yoff = ((unsigned)(jn * 256 + lane * 8)) ^
                          (((unsigned)jn & 7u) << 4);

    float h_loc[2] = {0.f, 0.f};

    // Prologue: zero h slots (2..5); stage x(0) into slot 0
    {
        uint4 z4 = make_uint4(0u, 0u, 0u, 0u);
#pragma unroll
        for (int c = 0; c < 4; c++)
            *((uint4*)(sZ + (2 + c) * ZBUF_BYTES) + tid) = z4;
        float4 vx0[2];
        const float* src = x_seq + (size_t)b0 * DIN;
        vx0[0] = *(const float4*)(src + (size_t)sm0 * DIN + sk0);
        vx0[1] = *(const float4*)(src + (size_t)sm1 * DIN + sk0);
        st_chunk(vx0, sZ, tid);
    }
    __syncthreads();

    for (int s = 0; s < T_STEPS; s++) {
        const int p = s & 1;

        // ---- issue next x LDG (entire step to land) ----
        float4 vx[2];
        if (s + 1 < T_STEPS) {
            const float* src = x_seq + ((size_t)(s + 1) * BATCH + b0) * DIN;
            vx[0] = *(const float4*)(src + (size_t)sm0 * DIN + sk0);
            vx[1] = *(const float4*)(src + (size_t)sm1 * DIN + sk0);
        }

        // ---- WAIT: monotonic count >= 16*s (all step-(s-1) arrivals) ----
        if (s > 0 && tid == 0) {
            const unsigned need = (unsigned)(P_N * s);
            unsigned v;
            do {
                asm volatile("ld.acquire.gpu.global.u32 %0, [%1];"
                             : "=r"(v) : "l"(&g_count[gb]) : "memory");
            } while (v < need);
        }
        __syncthreads();                      // BAR 1

        float acc[4][4] = {};
        const unsigned x0off = (unsigned)(p * ZBUF_BYTES);

        if (s > 0) {
            // ---- pair-slice cp.async of this pair's kg columns (2 groups) ----
            const char* hb = &g_hz[p][gb][0][0];
#pragma unroll
            for (int c = 0; c < 2; c++)       // slots 2,3
                asm volatile("cp.async.cg.shared.global [%0], [%1], 16;"
                             :: "r"(zsh + (unsigned)(2 + c) * ZBUF_BYTES + csoff),
                                "l"(hb + (size_t)c * ZBUF_BYTES + csoff) : "memory");
            asm volatile("cp.async.commit_group;" ::: "memory");
#pragma unroll
            for (int c = 2; c < 4; c++)       // slots 4,5
                asm volatile("cp.async.cg.shared.global [%0], [%1], 16;"
                             :: "r"(zsh + (unsigned)(2 + c) * ZBUF_BYTES + csoff),
                                "l"(hb + (size_t)c * ZBUF_BYTES + csoff) : "memory");
            asm volatile("cp.async.commit_group;" ::: "memory");
        }

        // ---- chunk-0 MMA (x slot p, local) fills group-1 latency ----
#pragma unroll
        for (int t = 0; t < 2; t++) {
            unsigned a0, a1, a2, a3;
            ldsm_x4(a0, a1, a2, a3, aoff[t] + x0off);
#pragma unroll
            for (int tp = 0; tp < 2; tp++) {
                mma_f16(acc[tp * 2 + 0], a0, a1, a2, a3, bf[t][tp].x, bf[t][tp].y);
                mma_f16(acc[tp * 2 + 1], a0, a1, a2, a3, bf[t][tp].z, bf[t][tp].w);
            }
        }

        // ---- pair-local wait: slots 2,3 slice staged (named barrier) ----
        if (s > 0) {
            asm volatile("cp.async.wait_group 1;" ::: "memory");
            asm volatile("bar.sync %0, 64;" :: "r"(wk + 1) : "memory");
        }

        // ---- chunks 1..2 MMA (slots 2,3) fill group-2 latency ----
#pragma unroll
        for (int t = 2; t < 6; t++) {
            unsigned c = (unsigned)(t >> 1);  // 1..2
            unsigned a0, a1, a2, a3;
            ldsm_x4(a0, a1, a2, a3, aoff[t & 1] + (c + 1) * ZBUF_BYTES);
#pragma unroll
            for (int tp = 0; tp < 2; tp++) {
                mma_f16(acc[tp * 2 + 0], a0, a1, a2, a3, bf[t][tp].x, bf[t][tp].y);
                mma_f16(acc[tp * 2 + 1], a0, a1, a2, a3, bf[t][tp].z, bf[t][tp].w);
            }
        }

        if (s > 0) {
            asm volatile("cp.async.wait_group 0;" ::: "memory");
            asm volatile("bar.sync %0, 64;" :: "r"(wk + 1) : "memory");
        }

        // ---- chunks 3..4 MMA (slots 4,5) ----
#pragma unroll
        for (int t = 6; t < 10; t++) {
            unsigned c = (unsigned)(t >> 1);  // 3..4
            unsigned a0, a1, a2, a3;
            ldsm_x4(a0, a1, a2, a3, aoff[t & 1] + (c + 1) * ZBUF_BYTES);
#pragma unroll
            for (int tp = 0; tp < 2; tp++) {
                mma_f16(acc[tp * 2 + 0], a0, a1, a2, a3, bf[t][tp].x, bf[t][tp].y);
                mma_f16(acc[tp * 2 + 1], a0, a1, a2, a3, bf[t][tp].z, bf[t][tp].w);
            }
        }

        // ---- scatter partial accumulators to per-wk epilogue buffers ----
        {
            float* eb = sEpi + wk * 1056;
            int row = lane >> 2;              // 0..7
#pragma unroll
            for (int t = 0; t < 4; t++) {
                int col = wn * 32 + t * 8 + (lane & 3) * 2;
                *(float2*)&eb[row * 66 + col]       = make_float2(acc[t][0], acc[t][1]);
                *(float2*)&eb[(row + 8) * 66 + col] = make_float2(acc[t][2], acc[t][3]);
            }
        }
        __syncthreads();                      // BAR 2: sEpi complete

        // ---- epilogue: reduce wk partials, activations, h update ----
        float tau_sv[2];
        char* hz_base0 = hz_w0 + (size_t)(p ^ 1) * hz_buf_stride;
        char* hz_base1 = hz_w1 + (size_t)(p ^ 1) * hz_buf_stride;
#pragma unroll
        for (int i = 0; i < 2; i++) {
            int b  = i * 8 + wid;             // local batch row 0..15
            int nl = lane;
            float uc = sBc[nl], ut = sBt[nl];
#pragma unroll
            for (int q = 0; q < 4; q++) {
                uc += sEpi[q * 1056 + b * 66 + nl];
                ut += sEpi[q * 1056 + b * 66 + nl + 32];
            }
            float ea   = __expf(-2.f * fabsf(uc));
            float cand = copysignf(__fdividef(1.f - ea, 1.f + ea), uc);
            float sg   = __fdividef(1.f, 1.f + __expf(-ut));
            float tau  = 0.2f + 1.8f * sg;
            tau_sv[i]  = tau;
            float h    = h_loc[i];
            float hn   = h + 0.1f * __fdividef(cand - h, tau);
            h_loc[i]   = hn;
            *(__half*)(i == 0 ? hz_base0 : hz_base1) = __float2half_rn(hn);
        }

        // ---- BAR then ARRIVE IMMEDIATELY (peers' critical path) ----
        __syncthreads();                      // BAR 3: all h stores issued+ordered
        if (tid == 0) {
            unsigned old;
            asm volatile("atom.add.release.gpu.global.u32 %0, [%1], %2;"
                         : "=r"(old) : "l"(&g_count[gb]), "r"(1u) : "memory");
        }

        // ---- post-arrive tail (not on peers' critical path) ----
        // y(s-1): warp 0 dots staged h(s) row jn with Wo (slots 2..5 valid
        // until next step's cp.async, which is after next BAR 1)
        if (s > 0 && wid == 0) {
            float y = 0.f;
#pragma unroll
            for (int c = 0; c < 4; c++) {
                uint2 hh = *(const uint2*)(sZ + (2 + c) * ZBUF_BYTES + yoff);
                float4 w4 = *(const float4*)&sWo[c * 128 + lane * 4];
                float2 f0 = __half22float2(*(__half2*)&hh.x);
                float2 f1 = __half22float2(*(__half2*)&hh.y);
                y += f0.x * w4.x + f0.y * w4.y + f1.x * w4.z + f1.y * w4.w;
            }
#pragma unroll
            for (int o = 16; o; o >>= 1) y += __shfl_xor_sync(0xffffffffu, y, o);
            if (lane == 0) out[(size_t)(s - 1) * BATCH + b0 + jn] = y + bo_v;
        }
        // stage next x into slot p^1 (reads happen only after next BAR 1)
        if (s + 1 < T_STEPS) st_chunk(vx, sZ + (p ^ 1) * ZBUF_BYTES, tid);
        // tau stores (never read cross-CTA)
#pragma unroll
        for (int i = 0; i < 2; i++) {
            int b = i * 8 + wid;
            __stcs(&out[(size_t)T_STEPS * BATCH +
                        ((size_t)s * BATCH + b0 + b) * HID + n0 + lane], tau_sv[i]);
        }
    }

    // ---- final: wait for all step-511 arrivals, then y(511) from g_hz[0] ----
    if (tid == 0) {
        const unsigned need = (unsigned)(P_N * T_STEPS);
        unsigned v;
        do {
            asm volatile("ld.acquire.gpu.global.u32 %0, [%1];"
                         : "=r"(v) : "l"(&g_count[gb]) : "memory");
        } while (v < need);
    }
    __syncthreads();
    if (wid == 0) {
        const char* hb = (const char*)&g_hz[0][gb][0][0];
        float y = 0.f;
#pragma unroll
        for (int c = 0; c < 4; c++) {
            uint2 hh = __ldcg((const uint2*)(hb + c * ZBUF_BYTES + yoff));
            float4 w4 = *(const float4*)&sWo[c * 128 + lane * 4];
            float2 f0 = __half22float2(*(__half2*)&hh.x);
            float2 f1 = __half22float2(*(__half2*)&hh.y);
            y += f0.x * w4.x + f0.y * w4.y + f1.x * w4.z + f1.y * w4.w;
        }
#pragma unroll
        for (int o = 16; o; o >>= 1) y += __shfl_xor_sync(0xffffffffu, y, o);
        if (lane == 0) out[(size_t)(T_STEPS - 1) * BATCH + b0 + jn] = y + bo_v;
    }

    // ---- reset monotonic counters for the next graph replay ----
    if (tid == 0) {
        unsigned old;
        asm volatile("atom.add.release.gpu.global.u32 %0, [%1], %2;"
                     : "=r"(old) : "l"(&g_exit[gb]), "r"(1u) : "memory");
        if (old == P_N - 1u) {
            asm volatile("st.release.gpu.global.u32 [%0], %1;"
                         :: "l"(&g_count[gb]), "r"(0u) : "memory");
            asm volatile("st.release.gpu.global.u32 [%0], %1;"
                         :: "l"(&g_exit[gb]), "r"(0u) : "memory");
        }
    }
}

extern "C" void kernel_launch(void* const* d_in, const int* in_sizes, int n_in,
                              void* d_out, int out_size) {
    (void)in_sizes; (void)n_in; (void)out_size;
    const float* x_seq = (const float*)d_in[0];
    const float* Wc    = (const float*)d_in[1];
    const float* bc    = (const float*)d_in[2];
    const float* Wt    = (const float*)d_in[3];
    const float* bt    = (const float*)d_in[4];
    const float* Wo    = (const float*)d_in[5];
    const float* bo    = (const float*)d_in[6];
    float* out = (float*)d_out;

    cudaFuncSetAttribute(liquid_kernel, cudaFuncAttributeMaxDynamicSharedMemorySize, SMEM_BYTES);
    liquid_kernel<<<GRID, NTHREADS, SMEM_BYTES>>>(x_seq, Wc, bc, Wt, bt, Wo, bo, out);
}

// round 17
// speedup vs baseline: 1.3755x; 1.0070x over previous
#include <cuda_runtime.h>
#include <cuda_fp16.h>
#include <cstdint>

// Problem constants
#define T_STEPS 512
#define BATCH   256
#define DIN     128
#define HID     512
#define KTOT    640          // DIN + HID

// Tiling: 256 CTAs (2 per SM where paired). CTA (gb, jn): 16 batch rows, 32 H cols.
#define P_B 16               // batch groups
#define P_N 16               // n-slices per group
#define B_TILE 16            // batch rows per CTA (M)
#define N_SLICE 32           // H columns per CTA
#define NCHUNK 5             // 640 / 128
#define NKG 8                // kg16 groups per chunk
#define KGG_TOT 40           // 640 / 16
#define NTHREADS 256
#define GRID (P_B * P_N)     // 256

// Shared memory (uint32 units). Weight staging (20480 u32 = 80KB) is ALIASED
// over the runtime layout: it is only used during init, before z/epi exist.
#define OFF_WF  0            // staging: 40*4*32*4 = 20480 u32
#define OFF_Z   0            // 6 slots * 1024 u32 = 6144
#define OFF_EPI 6144         // 4 wk-buffers * 16*66 = 4224
#define OFF_BC  10368        // 32
#define OFF_BT  10400        // 32
#define OFF_WO  10432        // 512
#define SMEM_U32 20480
#define SMEM_BYTES (SMEM_U32 * 4)   // 81920 B -> 2 CTAs/SM

#define ZBUF_BYTES 4096      // 16 rows x 256 B

// Persistent device state.
// g_hz: hidden state fp16, PRE-SWIZZLED smem fragment layout, [buf][group][chunk].
// g_xz: PRE-CONVERTED x sequence, same layout: [step][group][4096B chunk].
__device__ __align__(16) char g_hz[2][P_B][4][ZBUF_BYTES];
__device__ __align__(16) char g_xz[(size_t)T_STEPS * P_B * ZBUF_BYTES];
__device__ unsigned g_count[P_B];   // MONOTONIC arrivals (16 init + 16/step); reset at end
__device__ unsigned g_exit[P_B];    // exit barrier for the reset

__device__ __forceinline__ void mma_f16(float* c, unsigned a0, unsigned a1,
                                        unsigned a2, unsigned a3,
                                        unsigned b0, unsigned b1) {
    asm("mma.sync.aligned.m16n8k16.row.col.f32.f16.f16.f32 "
        "{%0,%1,%2,%3},{%4,%5,%6,%7},{%8,%9},{%0,%1,%2,%3};"
        : "+f"(c[0]), "+f"(c[1]), "+f"(c[2]), "+f"(c[3])
        : "r"(a0), "r"(a1), "r"(a2), "r"(a3), "r"(b0), "r"(b1));
}

__device__ __forceinline__ void ldsm_x4(unsigned& a0, unsigned& a1,
                                        unsigned& a2, unsigned& a3, unsigned saddr) {
    asm volatile("ldmatrix.sync.aligned.m8n8.x4.shared.b16 {%0,%1,%2,%3}, [%4];"
                 : "=r"(a0), "=r"(a1), "=r"(a2), "=r"(a3) : "r"(saddr));
}

__global__ void __launch_bounds__(NTHREADS, 2)
liquid_kernel(const float* __restrict__ x_seq,
              const float* __restrict__ Wc, const float* __restrict__ bc,
              const float* __restrict__ Wt, const float* __restrict__ bt,
              const float* __restrict__ Wo, const float* __restrict__ bo,
              float* __restrict__ out) {
    extern __shared__ unsigned smem[];
    unsigned* sWf  = smem + OFF_WF;      // init only (aliased)
    char*     sZ   = (char*)(smem + OFF_Z);
    float*    sEpi = (float*)(smem + OFF_EPI);
    float*    sBc  = (float*)(smem + OFF_BC);
    float*    sBt  = (float*)(smem + OFF_BT);
    float*    sWo  = (float*)(smem + OFF_WO);

    const int tid  = threadIdx.x;
    const int gb   = blockIdx.x / P_N;   // batch group 0..15
    const int jn   = blockIdx.x % P_N;   // n-slice 0..15
    const int b0   = gb * B_TILE;
    const int n0   = jn * N_SLICE;
    const int lane = tid & 31;
    const int wid  = tid >> 5;           // 0..7
    const int wn   = wid & 1;            // N half (32 combined cols)
    const int wk   = wid >> 1;           // K quarter (2 kg16 per chunk)

    // ---- init: weights into B-fragment layout (fp16) in staging region ----
    for (int e = tid; e < KGG_TOT * 4 * 32 * 4; e += NTHREADS) {
        int q    = e & 3;
        int l    = (e >> 2) & 31;
        int ntp  = (e >> 7) & 3;
        int kgg  = e >> 9;
        int nt   = 2 * ntp + (q >> 1);
        int k0   = kgg * 16 + (l & 3) * 2 + (q & 1) * 8;
        int cc   = nt * 8 + (l >> 2);
        const float* W = (cc < N_SLICE) ? (Wc + n0 + cc) : (Wt + n0 + cc - N_SLICE);
        float w0 = W[(size_t)k0 * HID];
        float w1 = W[(size_t)(k0 + 1) * HID];
        __half2 h = __float22half2_rn(make_float2(w0, w1));
        sWf[e] = *(unsigned*)&h;
    }
    __syncthreads();

    // ---- this warp's B fragments -> REGISTERS (persistent) ----
    uint4 bf[10][2];
#pragma unroll
    for (int t = 0; t < 10; t++) {
        int kgg = (t >> 1) * NKG + wk * 2 + (t & 1);
#pragma unroll
        for (int tp = 0; tp < 2; tp++) {
            int ntp = wn * 2 + tp;
            bf[t][tp] = *(const uint4*)(sWf + ((kgg * 4 + ntp) * 32 + lane) * 4);
        }
    }
    __syncthreads();   // ALL reads of staging done before aliased writes below

    // ---- runtime smem init (aliased over staging) ----
    if (tid < N_SLICE) { sBc[tid] = bc[n0 + tid]; sBt[tid] = bt[n0 + tid]; }
#pragma unroll
    for (int r = 0; r < 2; r++) sWo[r * NTHREADS + tid] = Wo[r * NTHREADS + tid];
    const float bo_v = bo[0];

    // ---- pre-convert this CTA's share of x into g_xz (fp16, pre-swizzled) ----
    // CTA (gb, jn) converts steps si = jn, jn+16, ... for its own group gb.
    for (int si = jn; si < T_STEPS; si += P_N) {
        const float* src = x_seq + ((size_t)si * BATCH + b0) * DIN;
        char* dstb = g_xz + ((size_t)si * P_B + gb) * ZBUF_BYTES;
#pragma unroll
        for (int i = 0; i < 2; i++) {
            int f  = i * NTHREADS + tid;
            int m  = f >> 5;
            int k4 = (f & 31) * 4;
            float4 v = *(const float4*)(src + (size_t)m * DIN + k4);
            unsigned off = (unsigned)(m * 256 + k4 * 2) ^ (((unsigned)m & 7u) << 4);
            __half2 h01 = __float22half2_rn(make_float2(v.x, v.y));
            __half2 h23 = __float22half2_rn(make_float2(v.z, v.w));
            uint2 pk;
            pk.x = *(unsigned*)&h01;
            pk.y = *(unsigned*)&h23;
            *(uint2*)(dstb + off) = pk;
        }
    }
    __syncthreads();
    // init arrival (+1 per CTA); group conversion complete when count >= 16
    if (tid == 0) {
        unsigned old;
        asm volatile("atom.add.release.gpu.global.u32 %0, [%1], %2;"
                     : "=r"(old) : "l"(&g_count[gb]), "r"(1u) : "memory");
        unsigned v;
        do {
            asm volatile("ld.acquire.gpu.global.u32 %0, [%1];"
                         : "=r"(v) : "l"(&g_count[gb]) : "memory");
        } while (v < (unsigned)P_N);
    }
    __syncthreads();

    // ldmatrix base offsets; swizzle on complete low-12-bit offset; slot adds
    // bits 12+ (carry-free).
    const int arow = ((lane >> 3) & 1) * 8 + (lane & 7);   // 0..15
    const int acol = ((lane >> 4) & 1) * 16;
    const unsigned zsh = (unsigned)__cvta_generic_to_shared(sZ);
    unsigned aoff[2];
#pragma unroll
    for (int i = 0; i < 2; i++) {
        int kg = wk * 2 + i;
        aoff[i] = zsh + (((unsigned)(arow * 256 + kg * 32 + acol)) ^
                         (((unsigned)arow & 7u) << 4));
    }

    // Pair-slice cp.async offset (h): pair wk copies rows 0..15 x its kg cols.
    const int lg   = wn * 32 + lane;
    const int crow = lg >> 2;
    const unsigned csoff = ((unsigned)(crow * 256 + wk * 64 + (lg & 3) * 16)) ^
                           (((unsigned)crow & 7u) << 4);

    // Epilogue h-store pointers (2 elements: rows wid and 8+wid, col n0+lane)
    const int hcol = n0 + lane;
    char* const hz_w0 = &g_hz[0][gb][hcol >> 7]
        [((unsigned)((wid) * 256 + (hcol & 127) * 2)) ^ (((unsigned)wid & 7u) << 4)];
    char* const hz_w1 = &g_hz[0][gb][hcol >> 7]
        [((unsigned)((8 + wid) * 256 + (hcol & 127) * 2)) ^ (((unsigned)(8 + wid) & 7u) << 4)];
    const size_t hz_buf_stride = (size_t)P_B * 4 * ZBUF_BYTES;

    // y-dot row offset (warp 0 computes group row jn)
    const unsigned yoff = ((unsigned)(jn * 256 + lane * 8)) ^
                          (((unsigned)jn & 7u) << 4);

    float h_loc[2] = {0.f, 0.f};

    // Prologue: zero h slots (2..5); cp.async x(0) into slot 0 (identity copy)
    {
        uint4 z4 = make_uint4(0u, 0u, 0u, 0u);
#pragma unroll
        for (int c = 0; c < 4; c++)
            *((uint4*)(sZ + (2 + c) * ZBUF_BYTES) + tid) = z4;
        const char* xb = g_xz + (size_t)gb * ZBUF_BYTES;   // step 0
        asm volatile("cp.async.cg.shared.global [%0], [%1], 16;"
                     :: "r"(zsh + (unsigned)tid * 16u),
                        "l"(xb + (size_t)tid * 16) : "memory");
        asm volatile("cp.async.commit_group;" ::: "memory");
        asm volatile("cp.async.wait_group 0;" ::: "memory");
    }
    __syncthreads();

    for (int s = 0; s < T_STEPS; s++) {
        const int p = s & 1;

        // ---- WAIT: monotonic count >= 16 init + 16*s step arrivals ----
        if (s > 0 && tid == 0) {
            const unsigned need = (unsigned)(P_N * (s + 1));
            unsigned v;
            do {
                asm volatile("ld.acquire.gpu.global.u32 %0, [%1];"
                             : "=r"(v) : "l"(&g_count[gb]) : "memory");
            } while (v < need);
        }
        __syncthreads();                      // BAR 1

        float acc[4][4] = {};
        const unsigned x0off = (unsigned)(p * ZBUF_BYTES);

        // ---- G1: pair-slice h slots 2,3 (empty group at s==0) ----
        const char* hb = &g_hz[p][gb][0][0];
        if (s > 0) {
#pragma unroll
            for (int c = 0; c < 2; c++)
                asm volatile("cp.async.cg.shared.global [%0], [%1], 16;"
                             :: "r"(zsh + (unsigned)(2 + c) * ZBUF_BYTES + csoff),
                                "l"(hb + (size_t)c * ZBUF_BYTES + csoff) : "memory");
        }
        asm volatile("cp.async.commit_group;" ::: "memory");
        // ---- G2: pair-slice h slots 4,5 + block-slice x(s+1) -> slot p^1 ----
        if (s > 0) {
#pragma unroll
            for (int c = 2; c < 4; c++)
                asm volatile("cp.async.cg.shared.global [%0], [%1], 16;"
                             :: "r"(zsh + (unsigned)(2 + c) * ZBUF_BYTES + csoff),
                                "l"(hb + (size_t)c * ZBUF_BYTES + csoff) : "memory");
        }
        if (s + 1 < T_STEPS) {
            const char* xb = g_xz + ((size_t)(s + 1) * P_B + gb) * ZBUF_BYTES;
            asm volatile("cp.async.cg.shared.global [%0], [%1], 16;"
                         :: "r"(zsh + (unsigned)(p ^ 1) * ZBUF_BYTES + (unsigned)tid * 16u),
                            "l"(xb + (size_t)tid * 16) : "memory");
        }
        asm volatile("cp.async.commit_group;" ::: "memory");

        // ---- chunk-0 MMA (x slot p, local) fills G1 latency ----
#pragma unroll
        for (int t = 0; t < 2; t++) {
            unsigned a0, a1, a2, a3;
            ldsm_x4(a0, a1, a2, a3, aoff[t] + x0off);
#pragma unroll
            for (int tp = 0; tp < 2; tp++) {
                mma_f16(acc[tp * 2 + 0], a0, a1, a2, a3, bf[t][tp].x, bf[t][tp].y);
                mma_f16(acc[tp * 2 + 1], a0, a1, a2, a3, bf[t][tp].z, bf[t][tp].w);
            }
        }

        // ---- pair-local wait: G1 done (slots 2,3 slice staged) ----
        asm volatile("cp.async.wait_group 1;" ::: "memory");
        asm volatile("bar.sync %0, 64;" :: "r"(wk + 1) : "memory");

        // ---- chunks 1..2 MMA (slots 2,3) fill G2 latency ----
#pragma unroll
        for (int t = 2; t < 6; t++) {
            unsigned c = (unsigned)(t >> 1);  // 1..2
            unsigned a0, a1, a2, a3;
            ldsm_x4(a0, a1, a2, a3, aoff[t & 1] + (c + 1) * ZBUF_BYTES);
#pragma unroll
            for (int tp = 0; tp < 2; tp++) {
                mma_f16(acc[tp * 2 + 0], a0, a1, a2, a3, bf[t][tp].x, bf[t][tp].y);
                mma_f16(acc[tp * 2 + 1], a0, a1, a2, a3, bf[t][tp].z, bf[t][tp].w);
            }
        }

        asm volatile("cp.async.wait_group 0;" ::: "memory");
        asm volatile("bar.sync %0, 64;" :: "r"(wk + 1) : "memory");

        // ---- chunks 3..4 MMA (slots 4,5) ----
#pragma unroll
        for (int t = 6; t < 10; t++) {
            unsigned c = (unsigned)(t >> 1);  // 3..4
            unsigned a0, a1, a2, a3;
            ldsm_x4(a0, a1, a2, a3, aoff[t & 1] + (c + 1) * ZBUF_BYTES);
#pragma unroll
            for (int tp = 0; tp < 2; tp++) {
                mma_f16(acc[tp * 2 + 0], a0, a1, a2, a3, bf[t][tp].x, bf[t][tp].y);
                mma_f16(acc[tp * 2 + 1], a0, a1, a2, a3, bf[t][tp].z, bf[t][tp].w);
            }
        }

        // ---- scatter partial accumulators to per-wk epilogue buffers ----
        {
            float* eb = sEpi + wk * 1056;
            int row = lane >> 2;              // 0..7
#pragma unroll
            for (int t = 0; t < 4; t++) {
                int col = wn * 32 + t * 8 + (lane & 3) * 2;
                *(float2*)&eb[row * 66 + col]       = make_float2(acc[t][0], acc[t][1]);
                *(float2*)&eb[(row + 8) * 66 + col] = make_float2(acc[t][2], acc[t][3]);
            }
        }
        __syncthreads();                      // BAR 2: sEpi complete

        // ---- epilogue: reduce wk partials, activations, h update ----
        float tau_sv[2];
        char* hz_base0 = hz_w0 + (size_t)(p ^ 1) * hz_buf_stride;
        char* hz_base1 = hz_w1 + (size_t)(p ^ 1) * hz_buf_stride;
#pragma unroll
        for (int i = 0; i < 2; i++) {
            int b  = i * 8 + wid;             // local batch row 0..15
            int nl = lane;
            float uc = sBc[nl], ut = sBt[nl];
#pragma unroll
            for (int q = 0; q < 4; q++) {
                uc += sEpi[q * 1056 + b * 66 + nl];
                ut += sEpi[q * 1056 + b * 66 + nl + 32];
            }
            float ea   = __expf(-2.f * fabsf(uc));
            float cand = copysignf(__fdividef(1.f - ea, 1.f + ea), uc);
            float sg   = __fdividef(1.f, 1.f + __expf(-ut));
            float tau  = 0.2f + 1.8f * sg;
            tau_sv[i]  = tau;
            float h    = h_loc[i];
            float hn   = h + 0.1f * __fdividef(cand - h, tau);
            h_loc[i]   = hn;
            *(__half*)(i == 0 ? hz_base0 : hz_base1) = __float2half_rn(hn);
        }

        // ---- BAR then ARRIVE IMMEDIATELY (peers' critical path) ----
        __syncthreads();                      // BAR 3: all h stores issued+ordered
        if (tid == 0) {
            unsigned old;
            asm volatile("atom.add.release.gpu.global.u32 %0, [%1], %2;"
                         : "=r"(old) : "l"(&g_count[gb]), "r"(1u) : "memory");
        }

        // ---- post-arrive tail (short: y-dot + tau stores only) ----
        if (s > 0 && wid == 0) {
            float y = 0.f;
#pragma unroll
            for (int c = 0; c < 4; c++) {
                uint2 hh = *(const uint2*)(sZ + (2 + c) * ZBUF_BYTES + yoff);
                float4 w4 = *(const float4*)&sWo[c * 128 + lane * 4];
                float2 f0 = __half22float2(*(__half2*)&hh.x);
                float2 f1 = __half22float2(*(__half2*)&hh.y);
                y += f0.x * w4.x + f0.y * w4.y + f1.x * w4.z + f1.y * w4.w;
            }
#pragma unroll
            for (int o = 16; o; o >>= 1) y += __shfl_xor_sync(0xffffffffu, y, o);
            if (lane == 0) out[(size_t)(s - 1) * BATCH + b0 + jn] = y + bo_v;
        }
#pragma unroll
        for (int i = 0; i < 2; i++) {
            int b = i * 8 + wid;
            __stcs(&out[(size_t)T_STEPS * BATCH +
                        ((size_t)s * BATCH + b0 + b) * HID + n0 + lane], tau_sv[i]);
        }
    }

    // ---- final: wait for all step-511 arrivals, then y(511) from g_hz[0] ----
    if (tid == 0) {
        const unsigned need = (unsigned)(P_N * (T_STEPS + 1));
        unsigned v;
        do {
            asm volatile("ld.acquire.gpu.global.u32 %0, [%1];"
                         : "=r"(v) : "l"(&g_count[gb]) : "memory");
        } while (v < need);
    }
    __syncthreads();
    if (wid == 0) {
        const char* hb = (const char*)&g_hz[0][gb][0][0];
        float y = 0.f;
#pragma unroll
        for (int c = 0; c < 4; c++) {
            uint2 hh = __ldcg((const uint2*)(hb + c * ZBUF_BYTES + yoff));
            float4 w4 = *(const float4*)&sWo[c * 128 + lane * 4];
            float2 f0 = __half22float2(*(__half2*)&hh.x);
            float2 f1 = __half22float2(*(__half2*)&hh.y);
            y += f0.x * w4.x + f0.y * w4.y + f1.x * w4.z + f1.y * w4.w;
        }
#pragma unroll
        for (int o = 16; o; o >>= 1) y += __shfl_xor_sync(0xffffffffu, y, o);
        if (lane == 0) out[(size_t)(T_STEPS - 1) * BATCH + b0 + jn] = y + bo_v;
    }

    // ---- reset monotonic counters for the next graph replay ----
    if (tid == 0) {
        unsigned old;
        asm volatile("atom.add.release.gpu.global.u32 %0, [%1], %2;"
                     : "=r"(old) : "l"(&g_exit[gb]), "r"(1u) : "memory");
        if (old == P_N - 1u) {
            asm volatile("st.release.gpu.global.u32 [%0], %1;"
                         :: "l"(&g_count[gb]), "r"(0u) : "memory");
            asm volatile("st.release.gpu.global.u32 [%0], %1;"
                         :: "l"(&g_exit[gb]), "r"(0u) : "memory");
        }
    }
}

extern "C" void kernel_launch(void* const* d_in, const int* in_sizes, int n_in,
                              void* d_out, int out_size) {
    (void)in_sizes; (void)n_in; (void)out_size;
    const float* x_seq = (const float*)d_in[0];
    const float* Wc    = (const float*)d_in[1];
    const float* bc    = (const float*)d_in[2];
    const float* Wt    = (const float*)d_in[3];
    const float* bt    = (const float*)d_in[4];
    const float* Wo    = (const float*)d_in[5];
    const float* bo    = (const float*)d_in[6];
    float* out = (float*)d_out;

    cudaFuncSetAttribute(liquid_kernel, cudaFuncAttributeMaxDynamicSharedMemorySize, SMEM_BYTES);
    liquid_kernel<<<GRID, NTHREADS, SMEM_BYTES>>>(x_seq, Wc, bc, Wt, bt, Wo, bo, out);
}